// round 3
// baseline (speedup 1.0000x reference)
#include <cuda_runtime.h>
#include <cuda_bf16.h>
#include <cstdint>

// Problem constants
#define Bn 64
#define Tn 64
#define Dn 64
#define En 128
#define Hn 128
#define Pn 63   // prefixes 0..62

// ---------------- device scratch (allowed: __device__ globals) ----------------
__device__ float g_emb[Tn * Bn * En];            // [t][b][e]
__device__ float g_gia[Tn * Bn * 384];           // [t][b][u]  u = gate*128+k (r,z,n)
__device__ float g_gib[Tn * Bn * 384];
__device__ float g_WhaT[128 * 384];              // [i][u] = Wh_a[u][i]
__device__ float g_WhbT[128 * 384];
__device__ float g_WiaT[128 * 384];              // [e][u] = Wi_a[u][e]
__device__ float g_WibT[128 * 384];
__device__ float g_WbT[128 * 128];               // [i][e] = Wb[e][i]
__device__ float g_WembT[64 * 128];              // [d][e] = W_emb[e][d]
__device__ float g_WoWemb[128 * 64];             // [e][d] = Wo[e]*W_emb[e][d]

// ---------------- f32x2 helpers ----------------
__device__ __forceinline__ unsigned long long pack2(float x, float y) {
    unsigned long long r;
    asm("mov.b64 %0, {%1,%2};" : "=l"(r) : "f"(x), "f"(y));
    return r;
}
__device__ __forceinline__ float2 unpack2(unsigned long long v) {
    float2 r;
    asm("mov.b64 {%0,%1}, %2;" : "=f"(r.x), "=f"(r.y) : "l"(v));
    return r;
}
__device__ __forceinline__ unsigned long long fma2(unsigned long long a,
                                                   unsigned long long b,
                                                   unsigned long long c) {
    unsigned long long d;
    asm("fma.rn.f32x2 %0, %1, %2, %3;" : "=l"(d) : "l"(a), "l"(b), "l"(c));
    return d;
}

__device__ __forceinline__ float sigmoidf_(float v) {
    return __fdividef(1.f, 1.f + __expf(-v));
}
__device__ __forceinline__ float tanhfast(float v) {
    float e = __expf(2.f * v);
    return 1.f - __fdividef(2.f, e + 1.f);
}
__device__ __forceinline__ float gru_step(float ir, float iz, float in_,
                                          float hr, float hz, float hn, float h) {
    float r = sigmoidf_(ir + hr);
    float z = sigmoidf_(iz + hz);
    float n = tanhfast(in_ + r * hn);
    return n + z * (h - n);
}

// ---------------- prep: transposes ----------------
__global__ void prep_transpose(const float* __restrict__ Wh_a,
                               const float* __restrict__ Wh_b,
                               const float* __restrict__ Wi_a,
                               const float* __restrict__ Wi_b,
                               const float* __restrict__ Wb,
                               const float* __restrict__ W_emb,
                               const float* __restrict__ Wo) {
    int idx = blockIdx.x * blockDim.x + threadIdx.x;
    int stride = gridDim.x * blockDim.x;
    for (int n = idx; n < 128 * 384; n += stride) {
        int u = n % 384, i = n / 384;
        g_WhaT[n] = Wh_a[u * 128 + i];
        g_WhbT[n] = Wh_b[u * 128 + i];
        g_WiaT[n] = Wi_a[u * 128 + i];
        g_WibT[n] = Wi_b[u * 128 + i];
    }
    for (int n = idx; n < 128 * 128; n += stride) {
        int e = n % 128, i = n / 128;
        g_WbT[n] = Wb[e * 128 + i];
    }
    for (int n = idx; n < 64 * 128; n += stride) {
        int e = n % 128, d = n / 128;
        g_WembT[n] = W_emb[e * 64 + d];
    }
    for (int n = idx; n < 128 * 64; n += stride) {
        int d = n % 64, e = n / 64;
        g_WoWemb[n] = Wo[e] * W_emb[e * 64 + d];
    }
}

// ---------------- emb: [t][b][e] = sum_d x[b][t][d] * W_emb[e][d] + b_emb[e] ----------------
__global__ void emb_kernel(const float* __restrict__ x, const float* __restrict__ b_emb) {
    __shared__ float xs[64];
    int tb = blockIdx.x;                 // t*64 + b
    int t_ = tb >> 6, b = tb & 63;
    int e = threadIdx.x;                 // 128 threads
    if (e < 64) xs[e] = x[((size_t)b * Tn + t_) * Dn + e];
    __syncthreads();
    float acc = 0.f;
#pragma unroll 8
    for (int d = 0; d < 64; ++d) acc = fmaf(g_WembT[d * 128 + e], xs[d], acc);
    g_emb[(size_t)tb * 128 + e] = acc + b_emb[e];
}

// ---------------- gi: [t][b][u] = sum_e emb[t][b][e] * Wi[u][e] + bi[u], both GRUs ----------------
__global__ void gi_kernel(const float* __restrict__ bi_a, const float* __restrict__ bi_b) {
    __shared__ float es[128];
    int tb = blockIdx.x;
    int t = threadIdx.x;                 // 256 threads
    if (t < 128) es[t] = g_emb[(size_t)tb * 128 + t];
    __syncthreads();
    for (int u = t; u < 768; u += 256) {
        const float* WT;
        const float* bi;
        float* out;
        int uu;
        if (u < 384) { WT = g_WiaT; bi = bi_a; out = g_gia; uu = u; }
        else         { WT = g_WibT; bi = bi_b; out = g_gib; uu = u - 384; }
        float acc = 0.f;
#pragma unroll 8
        for (int e = 0; e < 128; ++e) acc = fmaf(WT[e * 384 + uu], es[e], acc);
        out[(size_t)tb * 384 + uu] = acc + bi[uu];
    }
}

// ---------------- main persistent kernel ----------------
// grid: 504 blocks = 63 prefixes (longest first) x 8 batch-chunks of 8 rows
// block: 256 threads
__global__ __launch_bounds__(256) void retain_main(
    const float* __restrict__ x,
    const float* __restrict__ bh_a, const float* __restrict__ bh_b,
    const float* __restrict__ Wa, const float* __restrict__ ba,
    const float* __restrict__ bb, const float* __restrict__ Wo,
    const float* __restrict__ bo, int nq, float* __restrict__ out) {

    __shared__ unsigned long long sh_h[2][2][4][128];  // [buf][gru][rowpair][i] -> packed rows (2rp,2rp+1)
    __shared__ float sh_beta[8][128];
    __shared__ float sh_ech[8][64];
    __shared__ float sh_preA[8], sh_scale[8], sh_w[8], sh_m[8], sh_l[8];

    const int t = threadIdx.x;
    const int pi = blockIdx.x >> 3;
    const int p = 62 - pi;               // longest prefixes scheduled first
    const int b0 = (blockIdx.x & 7) * 8;

    const int k = t & 127;
    const int gru = t >> 7;
    const int d_ = t & 63;
    const int g_ = t >> 6;               // 0..3

    // init hidden buffers + softmax state
    for (int n = t; n < 2 * 2 * 4 * 128; n += 256)
        ((unsigned long long*)sh_h)[n] = 0ull;
    if (t < 8) { sh_m[t] = -1e30f; sh_l[t] = 0.f; }
    float cacc[4] = {0.f, 0.f, 0.f, 0.f};
    float gacc[2] = {0.f, 0.f};
    __syncthreads();

    const float* WT  = gru ? g_WhbT : g_WhaT;
    const float* giT = gru ? g_gib  : g_gia;
    const float* bh  = gru ? bh_b   : bh_a;
    const float bhr = bh[k], bhz = bh[128 + k], bhn = bh[256 + k];
    const float ba0 = ba[0];

    for (int s = 0; s <= p; ++s) {
        const int j = p - s;
        const int cb = s & 1;
        const unsigned long long (*cur)[4][128] = sh_h[cb];
        unsigned long long (*nxt)[4][128] = sh_h[cb ^ 1];

        // ---- phase 1: gh = h @ Wh^T (both GRUs, rows packed in f32x2) ----
        unsigned long long aR[4], aZ[4], aN[4];
#pragma unroll
        for (int rp = 0; rp < 4; ++rp) { aR[rp] = 0ull; aZ[rp] = 0ull; aN[rp] = 0ull; }
        const float* Wrow = WT + k;
#pragma unroll 4
        for (int i = 0; i < 128; ++i) {
            float wr = Wrow[i * 384];
            float wz = Wrow[i * 384 + 128];
            float wn = Wrow[i * 384 + 256];
            unsigned long long wr2 = pack2(wr, wr);
            unsigned long long wz2 = pack2(wz, wz);
            unsigned long long wn2 = pack2(wn, wn);
#pragma unroll
            for (int rp = 0; rp < 4; ++rp) {
                unsigned long long h2 = cur[gru][rp][i];
                aR[rp] = fma2(wr2, h2, aR[rp]);
                aZ[rp] = fma2(wz2, h2, aZ[rp]);
                aN[rp] = fma2(wn2, h2, aN[rp]);
            }
        }
        // ---- phase 2: GRU cell update ----
        const float* gi0 = giT + ((size_t)(j * 64 + b0)) * 384 + k;
#pragma unroll
        for (int rp = 0; rp < 4; ++rp) {
            float2 hr = unpack2(aR[rp]);
            float2 hz = unpack2(aZ[rp]);
            float2 hn = unpack2(aN[rp]);
            float2 ho = unpack2(cur[gru][rp][k]);
            const float* giA = gi0 + (size_t)(2 * rp) * 384;
            const float* giB = gi0 + (size_t)(2 * rp + 1) * 384;
            float hx = gru_step(giA[0], giA[128], giA[256],
                                hr.x + bhr, hz.x + bhz, hn.x + bhn, ho.x);
            float hy = gru_step(giB[0], giB[128], giB[256],
                                hr.y + bhr, hz.y + bhz, hn.y + bhn, ho.y);
            nxt[gru][rp][k] = pack2(hx, hy);
        }
        __syncthreads();

        // ---- phase 3a: beta = tanh(0.5*h_b @ Wb^T + bb); preA = 0.5*Wa.h_a + ba ----
        {
            const int rp0 = gru * 2, rp1 = rp0 + 1;
            unsigned long long acc0 = 0ull, acc1 = 0ull;
#pragma unroll 4
            for (int i = 0; i < 128; ++i) {
                float wb = g_WbT[i * 128 + k];
                unsigned long long wb2 = pack2(wb, wb);
                acc0 = fma2(wb2, nxt[1][rp0][i], acc0);
                acc1 = fma2(wb2, nxt[1][rp1][i], acc1);
            }
            float bbv = bb[k];
            float2 a0 = unpack2(acc0), a1 = unpack2(acc1);
            sh_beta[rp0 * 2 + 0][k] = tanhfast(fmaf(0.5f, a0.x, bbv));
            sh_beta[rp0 * 2 + 1][k] = tanhfast(fmaf(0.5f, a0.y, bbv));
            sh_beta[rp1 * 2 + 0][k] = tanhfast(fmaf(0.5f, a1.x, bbv));
            sh_beta[rp1 * 2 + 1][k] = tanhfast(fmaf(0.5f, a1.y, bbv));
        }
        {
            const int r = t >> 5, lane = t & 31;
            float part = 0.f;
#pragma unroll
            for (int ii = 0; ii < 4; ++ii) {
                int i = lane + 32 * ii;
                float2 hv = unpack2(nxt[0][r >> 1][i]);
                part = fmaf(Wa[i], (r & 1) ? hv.y : hv.x, part);
            }
#pragma unroll
            for (int o = 16; o; o >>= 1) part += __shfl_xor_sync(0xffffffffu, part, o);
            if (lane == 0) sh_preA[r] = fmaf(0.5f, part, ba0);
        }
        __syncthreads();

        // ---- phase 3b: online-softmax scalars + e_chain = beta @ WoWemb ----
        if (t < 8) {
            float pa = sh_preA[t], mo = sh_m[t];
            float mn = fmaxf(mo, pa);
            float sc = __expf(mo - mn);
            float w = __expf(pa - mn);
            sh_scale[t] = sc;
            sh_w[t] = w;
            sh_l[t] = sh_l[t] * sc + w;
            sh_m[t] = mn;
        }
        {
            unsigned long long acc = 0ull;
#pragma unroll 4
            for (int e = 0; e < 128; ++e) {
                float wc = g_WoWemb[e * 64 + d_];
                unsigned long long b2 = pack2(sh_beta[g_][e], sh_beta[g_ + 4][e]);
                acc = fma2(pack2(wc, wc), b2, acc);
            }
            float2 av = unpack2(acc);
            sh_ech[g_][d_] = av.x;
            sh_ech[g_ + 4][d_] = av.y;
        }
        __syncthreads();

        // ---- phase 3c: accumulator updates ----
        {
            const float* eb = g_emb + ((size_t)(j * 64 + b0)) * 128;
#pragma unroll
            for (int c = 0; c < 4; ++c) {
                int r = gru * 4 + c;
                float ev = eb[(size_t)r * 128 + k];
                cacc[c] = fmaf(cacc[c], sh_scale[r], sh_w[r] * sh_beta[r][k] * ev);
            }
#pragma unroll
            for (int c = 0; c < 2; ++c) {
                int r = g_ + 4 * c;
                float xv = x[((size_t)(b0 + r) * Tn + j) * Dn + d_];
                gacc[c] = fmaf(gacc[c], sh_scale[r], sh_w[r] * sh_ech[r][d_] * xv);
            }
        }
        // no sync needed here: next phase-1 only writes the buffer this
        // iteration already finished reading before the post-phase-2 barrier.
    }
    __syncthreads();

    // ---- finalize: pred + weight outputs ----
    const int base = Pn - nq;            // short + 1
    if (p < base) return;
    const int q = p - base;

    // stage cacc into sh_beta for the Wo reduction
#pragma unroll
    for (int c = 0; c < 4; ++c) sh_beta[gru * 4 + c][k] = cacc[c];
    __syncthreads();

    if (t < 8) {
        float sum = 0.f;
#pragma unroll 8
        for (int e = 0; e < 128; ++e) sum = fmaf(Wo[e], sh_beta[t][e], sum);
        out[(size_t)(b0 + t) * nq + q] = __fdividef(sum, sh_l[t]) + bo[0];
    }
    {
        float inv = __fdividef(1.f, (float)(p + 1));
        size_t wbase = (size_t)64 * nq;  // pred section size
#pragma unroll
        for (int c = 0; c < 2; ++c) {
            int r = g_ + 4 * c;
            out[wbase + ((size_t)(b0 + r) * nq + q) * 64 + d_] =
                __fdividef(gacc[c], sh_l[r]) * inv;
        }
    }
}

// ---------------- launch ----------------
extern "C" void kernel_launch(void* const* d_in, const int* in_sizes, int n_in,
                              void* d_out, int out_size) {
    const float* x     = (const float*)d_in[0];
    const float* W_emb = (const float*)d_in[1];
    const float* b_emb = (const float*)d_in[2];
    const float* Wi_a  = (const float*)d_in[3];
    const float* Wh_a  = (const float*)d_in[4];
    const float* bi_a  = (const float*)d_in[5];
    const float* bh_a  = (const float*)d_in[6];
    const float* Wi_b  = (const float*)d_in[7];
    const float* Wh_b  = (const float*)d_in[8];
    const float* bi_b  = (const float*)d_in[9];
    const float* bh_b  = (const float*)d_in[10];
    const float* Wa    = (const float*)d_in[11];
    const float* ba    = (const float*)d_in[12];
    const float* Wb    = (const float*)d_in[13];
    const float* bb    = (const float*)d_in[14];
    const float* Wo    = (const float*)d_in[15];
    const float* bo    = (const float*)d_in[16];
    float* out = (float*)d_out;

    // derive output slice length from out_size: out_size = B*nq*(1 + D) = 64*nq*65
    int nq = out_size / (64 * 65);       // = 60 for short=2

    prep_transpose<<<96, 256>>>(Wh_a, Wh_b, Wi_a, Wi_b, Wb, W_emb, Wo);
    emb_kernel<<<Tn * Bn, 128>>>(x, b_emb);
    gi_kernel<<<Tn * Bn, 256>>>(bi_a, bi_b);
    retain_main<<<Pn * 8, 256>>>(x, bh_a, bh_b, Wa, ba, bb, Wo, bo, nq, out);
}